// round 16
// baseline (speedup 1.0000x reference)
#include <cuda_runtime.h>
#include <cuda_fp16.h>
#include <cuda_bf16.h>
#include <cstdint>

#define NN 100000
#define EE 1600000
#define NEG_SLOPE 0.2f
#define LN_EPS 1e-5f
#define NCHUNK 98  // ceil(NN/1024)

// ---------------- scratch (device globals; no allocation allowed) ----------------
__device__ __half         g_feat16[(size_t)NN * 128]; // h @ W in fp16 (25.6 MB)
__device__ __nv_bfloat16  g_hHi[(size_t)NN * 128];    // bf16 hi split of h (25.6 MB)
__device__ __nv_bfloat16  g_hLo[(size_t)NN * 128];    // bf16 lo split of h (25.6 MB)
__device__ __nv_bfloat16  g_WtHi[128 * 128];          // Wt[n][k] hi
__device__ __nv_bfloat16  g_WtLo[128 * 128];          // Wt[n][k] lo
__device__ float   g_el[NN * 2];
__device__ float   g_er[NN * 2];
__device__ int     g_deg[NN];
__device__ int     g_rowptr[NN + 1];
__device__ int     g_cursor[NN];
__device__ int     g_chunk_sum[128];
__device__ int     g_chunk_excl[128];
__device__ int     g_srcIdx[EE];               // CSR: src index per edge (4B/edge)

__device__ __forceinline__ uint32_t pack_bf16(float a, float b) {
    __nv_bfloat162 t = __floats2bfloat162_rn(a, b);
    return *reinterpret_cast<uint32_t*>(&t);
}

// ---------------- 0: zero degree counters ----------------
__global__ void zero_deg_kernel() {
    int i = blockIdx.x * blockDim.x + threadIdx.x;
    if (i < NN) g_deg[i] = 0;
}

// ---------------- 0b: split h into bf16 hi/lo (streaming; output L2-warm for gemm) ----------------
__global__ void conv_h_kernel(const float* __restrict__ h) {
    size_t j = (size_t)blockIdx.x * blockDim.x + threadIdx.x;  // one float4
    if (j >= (size_t)NN * 32) return;
    float4 v = ((const float4*)h)[j];
    __nv_bfloat16 h0 = __float2bfloat16(v.x), h1 = __float2bfloat16(v.y);
    __nv_bfloat16 h2 = __float2bfloat16(v.z), h3 = __float2bfloat16(v.w);
    uint2 hv, lv;
    hv.x = pack_bf16(__bfloat162float(h0), __bfloat162float(h1));
    hv.y = pack_bf16(__bfloat162float(h2), __bfloat162float(h3));
    lv.x = pack_bf16(v.x - __bfloat162float(h0), v.y - __bfloat162float(h1));
    lv.y = pack_bf16(v.z - __bfloat162float(h2), v.w - __bfloat162float(h3));
    ((uint2*)g_hHi)[j] = hv;
    ((uint2*)g_hLo)[j] = lv;
}

// ---------------- 0c: transpose+split W (tiny) ----------------
__global__ void conv_w_kernel(const float* __restrict__ W) {
    int i = blockIdx.x * blockDim.x + threadIdx.x;  // i = n*128 + k
    if (i >= 128 * 128) return;
    int n = i >> 7, k = i & 127;
    float v = W[(size_t)k * 128 + n];
    __nv_bfloat16 hb = __float2bfloat16(v);
    g_WtHi[i] = hb;
    g_WtLo[i] = __float2bfloat16(v - __bfloat162float(hb));
}

// ================= tensor-core GEMM, tile 128x64, warp=32x32 (low smem traffic) =================
// grid = (ceil(NN/128), 2); blockIdx.y = head. 8 warps = 4 row-tiles(32) x 2 col-halves(32).
#define ASTR 272                 // bytes per padded bf16 row (136 halves)
#define SM_A_HI 0                // 128*272 = 34816
#define SM_A_LO 34816
#define SM_B_HI 69632            // 64*272 = 17408
#define SM_B_LO 87040
#define SM_ATTN_L 104448         // 64 floats
#define SM_ATTN_R 104704
#define SM_ELB 104960            // 128 rows x 2 partials
#define SM_ERB 105984
#define SM_TOTAL 107008

__device__ __forceinline__ void mma_bf16(float* d, uint32_t a0, uint32_t a1, uint32_t a2,
                                         uint32_t a3, uint32_t b0, uint32_t b1) {
    asm volatile(
        "mma.sync.aligned.m16n8k16.row.col.f32.bf16.bf16.f32 "
        "{%0,%1,%2,%3}, {%4,%5,%6,%7}, {%8,%9}, {%0,%1,%2,%3};"
        : "+f"(d[0]), "+f"(d[1]), "+f"(d[2]), "+f"(d[3])
        : "r"(a0), "r"(a1), "r"(a2), "r"(a3), "r"(b0), "r"(b1));
}

__global__ void __launch_bounds__(256, 2) gemm_tc_kernel(const float* __restrict__ attn_l,
                                                         const float* __restrict__ attn_r) {
    extern __shared__ char smem[];
    int tid = threadIdx.x;
    int lane = tid & 31, wid = tid >> 5;
    int row0 = blockIdx.x * 128;
    int head = blockIdx.y;
    int ncol0 = head * 64;

    if (tid < 64) {
        *(float*)(smem + SM_ATTN_L + tid * 4) = attn_l[ncol0 + tid];
        *(float*)(smem + SM_ATTN_R + tid * 4) = attn_r[ncol0 + tid];
    }
    // ---- stage A (128 rows): uint4 copies from pre-split global ----
    for (int job = tid; job < 128 * 16; job += 256) {
        int r = job >> 4, c = job & 15;
        int grow = row0 + r;
        uint4 hv = make_uint4(0, 0, 0, 0), lv = make_uint4(0, 0, 0, 0);
        if (grow < NN) {
            hv = *(const uint4*)(g_hHi + (size_t)grow * 128 + c * 8);
            lv = *(const uint4*)(g_hLo + (size_t)grow * 128 + c * 8);
        }
        *(uint4*)(smem + SM_A_HI + r * ASTR + c * 16) = hv;
        *(uint4*)(smem + SM_A_LO + r * ASTR + c * 16) = lv;
    }
    // ---- stage B (this head's 64 n-rows): uint4 copies ----
    for (int job = tid; job < 64 * 16; job += 256) {
        int n = job >> 4, c = job & 15;
        *(uint4*)(smem + SM_B_HI + n * ASTR + c * 16) =
            *(const uint4*)(g_WtHi + (ncol0 + n) * 128 + c * 8);
        *(uint4*)(smem + SM_B_LO + n * ASTR + c * 16) =
            *(const uint4*)(g_WtLo + (ncol0 + n) * 128 + c * 8);
    }
    __syncthreads();

    int g = lane >> 2, tg = lane & 3;
    int wrow = wid & 3;          // row-tile (32 rows each)
    int wcol = wid >> 2;         // col-half (32 cols)
    const char* Abase_hi = smem + SM_A_HI + (uint32_t)(wrow * 32 + g) * ASTR;
    const char* Abase_lo = smem + SM_A_LO + (uint32_t)(wrow * 32 + g) * ASTR;
    float d[2][4][4];
#pragma unroll
    for (int mr = 0; mr < 2; mr++)
#pragma unroll
        for (int nt = 0; nt < 4; nt++) {
            d[mr][nt][0] = d[mr][nt][1] = d[mr][nt][2] = d[mr][nt][3] = 0.f;
        }

#pragma unroll
    for (int ks = 0; ks < 8; ks++) {
        uint32_t kb = ks * 32 + tg * 4;
        uint32_t ah[2][4], al[2][4];
#pragma unroll
        for (int mr = 0; mr < 2; mr++) {
            uint32_t off = mr * 16 * ASTR;
            ah[mr][0] = *(const uint32_t*)(Abase_hi + off + kb);
            ah[mr][1] = *(const uint32_t*)(Abase_hi + off + 8 * ASTR + kb);
            ah[mr][2] = *(const uint32_t*)(Abase_hi + off + kb + 16);
            ah[mr][3] = *(const uint32_t*)(Abase_hi + off + 8 * ASTR + kb + 16);
            al[mr][0] = *(const uint32_t*)(Abase_lo + off + kb);
            al[mr][1] = *(const uint32_t*)(Abase_lo + off + 8 * ASTR + kb);
            al[mr][2] = *(const uint32_t*)(Abase_lo + off + kb + 16);
            al[mr][3] = *(const uint32_t*)(Abase_lo + off + 8 * ASTR + kb + 16);
        }
#pragma unroll
        for (int nt = 0; nt < 4; nt++) {
            uint32_t nb = (uint32_t)((wcol * 4 + nt) * 8 + g) * ASTR + kb;
            uint32_t bh0 = *(const uint32_t*)(smem + SM_B_HI + nb);
            uint32_t bh1 = *(const uint32_t*)(smem + SM_B_HI + nb + 16);
            uint32_t bl0 = *(const uint32_t*)(smem + SM_B_LO + nb);
            uint32_t bl1 = *(const uint32_t*)(smem + SM_B_LO + nb + 16);
#pragma unroll
            for (int mr = 0; mr < 2; mr++) {
                mma_bf16(d[mr][nt], ah[mr][0], ah[mr][1], ah[mr][2], ah[mr][3], bh0, bh1);
                mma_bf16(d[mr][nt], al[mr][0], al[mr][1], al[mr][2], al[mr][3], bh0, bh1);
                mma_bf16(d[mr][nt], ah[mr][0], ah[mr][1], ah[mr][2], ah[mr][3], bl0, bl1);
            }
        }
    }

    // ---- el/er partials over this warp's 32 cols, 32 rows ----
    const float* alp = (const float*)(smem + SM_ATTN_L);
    const float* arp = (const float*)(smem + SM_ATTN_R);
#pragma unroll
    for (int mr = 0; mr < 2; mr++) {
        float el0 = 0.f, er0 = 0.f, el1 = 0.f, er1 = 0.f;
#pragma unroll
        for (int nt = 0; nt < 4; nt++) {
            int c = wcol * 32 + nt * 8 + tg * 2;
            float a0 = alp[c], a1 = alp[c + 1], b0 = arp[c], b1 = arp[c + 1];
            el0 += d[mr][nt][0] * a0 + d[mr][nt][1] * a1;
            er0 += d[mr][nt][0] * b0 + d[mr][nt][1] * b1;
            el1 += d[mr][nt][2] * a0 + d[mr][nt][3] * a1;
            er1 += d[mr][nt][2] * b0 + d[mr][nt][3] * b1;
        }
#pragma unroll
        for (int off = 1; off <= 2; off <<= 1) {
            el0 += __shfl_xor_sync(0xffffffffu, el0, off);
            er0 += __shfl_xor_sync(0xffffffffu, er0, off);
            el1 += __shfl_xor_sync(0xffffffffu, el1, off);
            er1 += __shfl_xor_sync(0xffffffffu, er1, off);
        }
        if (tg == 0) {
            int r0l = wrow * 32 + mr * 16 + g, r1l = r0l + 8;
            ((float*)(smem + SM_ELB))[r0l * 2 + wcol] = el0;
            ((float*)(smem + SM_ELB))[r1l * 2 + wcol] = el1;
            ((float*)(smem + SM_ERB))[r0l * 2 + wcol] = er0;
            ((float*)(smem + SM_ERB))[r1l * 2 + wcol] = er1;
        }
    }

    // ---- feat: stage fp16 tile in A region ----
    __syncthreads();
#pragma unroll
    for (int mr = 0; mr < 2; mr++) {
        int r0l = wrow * 32 + mr * 16 + g, r1l = r0l + 8;
#pragma unroll
        for (int nt = 0; nt < 4; nt++) {
            int c = wcol * 32 + nt * 8 + tg * 2;
            __half2 q0 = __floats2half2_rn(d[mr][nt][0], d[mr][nt][1]);
            __half2 q1 = __floats2half2_rn(d[mr][nt][2], d[mr][nt][3]);
            *(__half2*)(smem + SM_A_HI + r0l * ASTR + c * 2) = q0;
            *(__half2*)(smem + SM_A_HI + r1l * ASTR + c * 2) = q1;
        }
    }
    __syncthreads();
    // combine el/er partials (threads 0-127, one row each)
    if (tid < 128) {
        int grow = row0 + tid;
        if (grow < NN) {
            float el = ((const float*)(smem + SM_ELB))[tid * 2] +
                       ((const float*)(smem + SM_ELB))[tid * 2 + 1];
            float er = ((const float*)(smem + SM_ERB))[tid * 2] +
                       ((const float*)(smem + SM_ERB))[tid * 2 + 1];
            g_el[2 * grow + head] = el;
            g_er[2 * grow + head] = er;
        }
    }
    // coalesced feat store: 128 rows x 8 chunks of 16B (this head's 64 cols)
    for (int job = tid; job < 128 * 8; job += 256) {
        int row = job >> 3, c = job & 7;
        int grow = row0 + row;
        if (grow < NN) {
            *(uint4*)(g_feat16 + (size_t)grow * 128 + ncol0 + c * 8) =
                *(const uint4*)(smem + SM_A_HI + row * ASTR + c * 16);
        }
    }
}

// ---------------- 2: degree histogram ----------------
__global__ void hist_kernel(const int* __restrict__ dst) {
    int e = blockIdx.x * blockDim.x + threadIdx.x;
    if (e < EE) atomicAdd(&g_deg[dst[e]], 1);
}

// ---------------- 3a: per-chunk sums (chunk = 1024) ----------------
__global__ void chunk_sum_kernel() {
    int b = blockIdx.x, t = threadIdx.x;
    int base = b * 1024;
    int s = 0;
    for (int j = t; j < 1024; j += 256) {
        int i = base + j;
        s += (i < NN) ? g_deg[i] : 0;
    }
    __shared__ int sh[8];
#pragma unroll
    for (int off = 16; off; off >>= 1) s += __shfl_xor_sync(0xffffffffu, s, off);
    if ((t & 31) == 0) sh[t >> 5] = s;
    __syncthreads();
    if (t < 32) {
        int v = (t < 8) ? sh[t] : 0;
#pragma unroll
        for (int off = 4; off; off >>= 1) v += __shfl_xor_sync(0xffffffffu, v, off);
        if (t == 0) g_chunk_sum[b] = v;
    }
}

// ---------------- 3b: scan chunk sums (1 block) ----------------
__global__ void scan_chunks_kernel() {
    __shared__ int sh[128];
    int t = threadIdx.x;
    int v = (t < NCHUNK) ? g_chunk_sum[t] : 0;
    sh[t] = v;
    __syncthreads();
    for (int off = 1; off < 128; off <<= 1) {
        int a = (t >= off) ? sh[t - off] : 0;
        __syncthreads();
        sh[t] += a;
        __syncthreads();
    }
    if (t < NCHUNK) g_chunk_excl[t] = sh[t] - v;
}

// ---------------- 3c: finalize row_ptr / cursor ----------------
__global__ void scan_final_kernel() {
    int i = blockIdx.x * 1024 + threadIdx.x;
    int lane = threadIdx.x & 31, wid = threadIdx.x >> 5;
    int v = (i < NN) ? g_deg[i] : 0;
    int x = v;
#pragma unroll
    for (int off = 1; off < 32; off <<= 1) {
        int y = __shfl_up_sync(0xffffffffu, x, off);
        if (lane >= off) x += y;
    }
    __shared__ int sh[32];
    if (lane == 31) sh[wid] = x;
    __syncthreads();
    if (wid == 0) {
        int y = sh[lane];
#pragma unroll
        for (int off = 1; off < 32; off <<= 1) {
            int z = __shfl_up_sync(0xffffffffu, y, off);
            if (lane >= off) y += z;
        }
        sh[lane] = y;
    }
    __syncthreads();
    int incl = x + (wid ? sh[wid - 1] : 0);
    int base = g_chunk_excl[blockIdx.x];
    if (i < NN) {
        int excl = base + incl - v;
        g_rowptr[i] = excl;
        g_cursor[i] = excl;
    }
    if (i == NN - 1) g_rowptr[NN] = base + incl;
}

// ---------------- 4: scatter src indices into CSR order (logit-free) ----------------
__global__ void scatter_idx_kernel(const int* __restrict__ src, const int* __restrict__ dst) {
    int e = blockIdx.x * blockDim.x + threadIdx.x;
    if (e >= EE) return;
    int d = dst[e];
    int p = atomicAdd(&g_cursor[d], 1);
    g_srcIdx[p] = src[e];
}

// ---------------- 5: per-node softmax-aggregate + fused LayerNorm (unroll 4) ----------------
__global__ void agg_ln_kernel(const float* __restrict__ bias, const float* __restrict__ gamma,
                              const float* __restrict__ beta, float* __restrict__ out) {
    int gwarp = (blockIdx.x * blockDim.x + threadIdx.x) >> 5;
    int lane = threadIdx.x & 31;
    if (gwarp >= NN) return;
    int beg = g_rowptr[gwarp], end = g_rowptr[gwarp + 1];
    int hh = (lane >= 16) ? 1 : 0;
    float er_d = g_er[2 * gwarp + hh];

    float4 acc = make_float4(0.f, 0.f, 0.f, 0.f);
    float wsum = 0.f;
    int i = beg;
    for (; i + 4 <= end; i += 4) {
        int s0 = g_srcIdx[i], s1 = g_srcIdx[i + 1], s2 = g_srcIdx[i + 2], s3 = g_srcIdx[i + 3];
        uint2 u0 = ((const uint2*)(g_feat16 + (size_t)s0 * 128))[lane];
        uint2 u1 = ((const uint2*)(g_feat16 + (size_t)s1 * 128))[lane];
        uint2 u2 = ((const uint2*)(g_feat16 + (size_t)s2 * 128))[lane];
        uint2 u3 = ((const uint2*)(g_feat16 + (size_t)s3 * 128))[lane];
        float e0 = g_el[2 * s0 + hh] + er_d;
        float e1 = g_el[2 * s1 + hh] + er_d;
        float e2 = g_el[2 * s2 + hh] + er_d;
        float e3 = g_el[2 * s3 + hh] + er_d;
        e0 = (e0 > 0.f) ? e0 : NEG_SLOPE * e0;
        e1 = (e1 > 0.f) ? e1 : NEG_SLOPE * e1;
        e2 = (e2 > 0.f) ? e2 : NEG_SLOPE * e2;
        e3 = (e3 > 0.f) ? e3 : NEG_SLOPE * e3;
        float w0 = __expf(e0), w1 = __expf(e1), w2 = __expf(e2), w3 = __expf(e3);
        float2 v0a = __half22float2(*(__half2*)&u0.x), v0b = __half22float2(*(__half2*)&u0.y);
        float2 v1a = __half22float2(*(__half2*)&u1.x), v1b = __half22float2(*(__half2*)&u1.y);
        float2 v2a = __half22float2(*(__half2*)&u2.x), v2b = __half22float2(*(__half2*)&u2.y);
        float2 v3a = __half22float2(*(__half2*)&u3.x), v3b = __half22float2(*(__half2*)&u3.y);
        wsum += (w0 + w1) + (w2 + w3);
        acc.x += w0 * v0a.x + w1 * v1a.x + w2 * v2a.x + w3 * v3a.x;
        acc.y += w0 * v0a.y + w1 * v1a.y + w2 * v2a.y + w3 * v3a.y;
        acc.z += w0 * v0b.x + w1 * v1b.x + w2 * v2b.x + w3 * v3b.x;
        acc.w += w0 * v0b.y + w1 * v1b.y + w2 * v2b.y + w3 * v3b.y;
    }
    for (; i < end; i++) {
        int s0 = g_srcIdx[i];
        uint2 u0 = ((const uint2*)(g_feat16 + (size_t)s0 * 128))[lane];
        float e0 = g_el[2 * s0 + hh] + er_d;
        e0 = (e0 > 0.f) ? e0 : NEG_SLOPE * e0;
        float w0 = __expf(e0);
        float2 v0a = __half22float2(*(__half2*)&u0.x);
        float2 v0b = __half22float2(*(__half2*)&u0.y);
        wsum += w0;
        acc.x += w0 * v0a.x; acc.y += w0 * v0a.y;
        acc.z += w0 * v0b.x; acc.w += w0 * v0b.y;
    }
    float inv = (end > beg) ? 1.0f / wsum : 0.f;

    float4 b4 = ((const float4*)bias)[lane];
    float4 x;
    x.x = acc.x * inv + b4.x; x.y = acc.y * inv + b4.y;
    x.z = acc.z * inv + b4.z; x.w = acc.w * inv + b4.w;

    float s = x.x + x.y + x.z + x.w;
#pragma unroll
    for (int off = 16; off; off >>= 1) s += __shfl_xor_sync(0xffffffffu, s, off);
    float mu = s * (1.f / 128.f);
    float dx0 = x.x - mu, dx1 = x.y - mu, dx2 = x.z - mu, dx3 = x.w - mu;
    float ss = dx0 * dx0 + dx1 * dx1 + dx2 * dx2 + dx3 * dx3;
#pragma unroll
    for (int off = 16; off; off >>= 1) ss += __shfl_xor_sync(0xffffffffu, ss, off);
    float istd = rsqrtf(ss * (1.f / 128.f) + LN_EPS);

    float4 g4 = ((const float4*)gamma)[lane];
    float4 be4 = ((const float4*)beta)[lane];
    float4 y;
    y.x = g4.x * dx0 * istd + be4.x;
    y.y = g4.y * dx1 * istd + be4.y;
    y.z = g4.z * dx2 * istd + be4.z;
    y.w = g4.w * dx3 * istd + be4.w;
    ((float4*)(out + (size_t)gwarp * 128))[lane] = y;
}

// ---------------- launch ----------------
extern "C" void kernel_launch(void* const* d_in, const int* in_sizes, int n_in,
                              void* d_out, int out_size) {
    const float* h      = (const float*)d_in[0];
    const int*   src    = (const int*)d_in[1];
    const int*   dst    = (const int*)d_in[2];
    const float* W      = (const float*)d_in[3];
    const float* attn_l = (const float*)d_in[4];
    const float* attn_r = (const float*)d_in[5];
    const float* bias   = (const float*)d_in[6];
    const float* gamma  = (const float*)d_in[7];
    const float* beta   = (const float*)d_in[8];
    float* out = (float*)d_out;

    static cudaStream_t s1 = nullptr;
    static cudaEvent_t evRoot = nullptr, evSide = nullptr;
    if (!s1) {
        cudaStreamCreateWithFlags(&s1, cudaStreamNonBlocking);
        cudaEventCreateWithFlags(&evRoot, cudaEventDisableTiming);
        cudaEventCreateWithFlags(&evSide, cudaEventDisableTiming);
    }
    cudaFuncSetAttribute(gemm_tc_kernel, cudaFuncAttributeMaxDynamicSharedMemorySize, SM_TOTAL);

    // fork point
    cudaEventRecord(evRoot, 0);
    cudaStreamWaitEvent(s1, evRoot, 0);

    // submit: side kernel 0, then main prep+gemm (gemm = submission index 3 for ncu)
    zero_deg_kernel<<<(NN + 255) / 256, 256, 0, s1>>>();               // idx 0
    conv_h_kernel<<<(NN * 32 + 255) / 256, 256>>>(h);                  // idx 1 (main)
    conv_w_kernel<<<64, 256>>>(W);                                     // idx 2 (main)
    {
        dim3 grid((NN + 127) / 128, 2);
        gemm_tc_kernel<<<grid, 256, SM_TOTAL>>>(attn_l, attn_r);       // idx 3 (main)
    }

    // remaining side chain on s1
    hist_kernel<<<(EE + 255) / 256, 256, 0, s1>>>(dst);
    chunk_sum_kernel<<<NCHUNK, 256, 0, s1>>>();
    scan_chunks_kernel<<<1, 128, 0, s1>>>();
    scan_final_kernel<<<NCHUNK, 1024, 0, s1>>>();
    scatter_idx_kernel<<<(EE + 255) / 256, 256, 0, s1>>>(src, dst);
    cudaEventRecord(evSide, s1);

    // join: agg needs feat+el/er (main) + srcIdx (side)
    cudaStreamWaitEvent(0, evSide, 0);
    agg_ln_kernel<<<(NN * 32 + 255) / 256, 256>>>(bias, gamma, beta, out);
}

// round 17
// speedup vs baseline: 1.0276x; 1.0276x over previous
#include <cuda_runtime.h>
#include <cuda_fp16.h>
#include <cuda_bf16.h>
#include <cstdint>

#define NN 100000
#define EE 1600000
#define NEG_SLOPE 0.2f
#define LN_EPS 1e-5f
#define NCHUNK 98  // ceil(NN/1024)

// ---------------- scratch (device globals; no allocation allowed) ----------------
__device__ __half         g_feat16[(size_t)NN * 128]; // h @ W in fp16 (25.6 MB)
__device__ __nv_bfloat16  g_hHi[(size_t)NN * 128];    // bf16 hi split of h (25.6 MB)
__device__ __nv_bfloat16  g_hLo[(size_t)NN * 128];    // bf16 lo split of h (25.6 MB)
__device__ __nv_bfloat16  g_WtHi[128 * 128];          // Wt[n][k] hi
__device__ __nv_bfloat16  g_WtLo[128 * 128];          // Wt[n][k] lo
__device__ float   g_el[NN * 2];
__device__ float   g_er[NN * 2];
__device__ int     g_deg[NN];
__device__ int     g_rowptr[NN + 1];
__device__ int     g_cursor[NN];
__device__ int     g_chunk_sum[128];
__device__ int     g_chunk_excl[128];
__device__ int     g_srcIdx[EE];               // CSR: src index per edge (4B/edge)

__device__ __forceinline__ uint32_t pack_bf16(float a, float b) {
    __nv_bfloat162 t = __floats2bfloat162_rn(a, b);
    return *reinterpret_cast<uint32_t*>(&t);
}
__device__ __forceinline__ void cp_async16(uint32_t smem_addr, const void* gptr, uint32_t src_bytes) {
    asm volatile("cp.async.ca.shared.global [%0], [%1], 16, %2;"
                 :: "r"(smem_addr), "l"(gptr), "r"(src_bytes));
}

// ---------------- 0: zero degree counters ----------------
__global__ void zero_deg_kernel() {
    int i = blockIdx.x * blockDim.x + threadIdx.x;
    if (i < NN) g_deg[i] = 0;
}

// ---------------- 0b: split h into bf16 hi/lo (streaming; output L2-warm for gemm) ----------------
__global__ void conv_h_kernel(const float* __restrict__ h) {
    size_t j = (size_t)blockIdx.x * blockDim.x + threadIdx.x;  // one float4
    if (j >= (size_t)NN * 32) return;
    float4 v = ((const float4*)h)[j];
    __nv_bfloat16 h0 = __float2bfloat16(v.x), h1 = __float2bfloat16(v.y);
    __nv_bfloat16 h2 = __float2bfloat16(v.z), h3 = __float2bfloat16(v.w);
    uint2 hv, lv;
    hv.x = pack_bf16(__bfloat162float(h0), __bfloat162float(h1));
    hv.y = pack_bf16(__bfloat162float(h2), __bfloat162float(h3));
    lv.x = pack_bf16(v.x - __bfloat162float(h0), v.y - __bfloat162float(h1));
    lv.y = pack_bf16(v.z - __bfloat162float(h2), v.w - __bfloat162float(h3));
    ((uint2*)g_hHi)[j] = hv;
    ((uint2*)g_hLo)[j] = lv;
}

// ---------------- 0c: transpose+split W (tiny) ----------------
__global__ void conv_w_kernel(const float* __restrict__ W) {
    int i = blockIdx.x * blockDim.x + threadIdx.x;  // i = n*128 + k
    if (i >= 128 * 128) return;
    int n = i >> 7, k = i & 127;
    float v = W[(size_t)k * 128 + n];
    __nv_bfloat16 hb = __float2bfloat16(v);
    g_WtHi[i] = hb;
    g_WtLo[i] = __float2bfloat16(v - __bfloat162float(hb));
}

// ================= tensor-core GEMM, tile 64x64, 3 CTAs/SM, cp.async staging =================
// grid = (ceil(NN/64), 2); blockIdx.y = head. 8 warps = 4 row-tiles x 2 col-halves.
#define ASTR 272                 // bytes per padded bf16 row (136 halves)
#define SM_A_HI 0                // 64*272 = 17408
#define SM_A_LO 17408
#define SM_B_HI 34816            // 64*272 = 17408
#define SM_B_LO 52224
#define SM_ATTN_L 69632          // 64 floats
#define SM_ATTN_R 69888
#define SM_ELB 70144             // 64 rows x 2 partials
#define SM_ERB 70656
#define SM_TOTAL 71168

__device__ __forceinline__ void mma_bf16(float* d, uint32_t a0, uint32_t a1, uint32_t a2,
                                         uint32_t a3, uint32_t b0, uint32_t b1) {
    asm volatile(
        "mma.sync.aligned.m16n8k16.row.col.f32.bf16.bf16.f32 "
        "{%0,%1,%2,%3}, {%4,%5,%6,%7}, {%8,%9}, {%0,%1,%2,%3};"
        : "+f"(d[0]), "+f"(d[1]), "+f"(d[2]), "+f"(d[3])
        : "r"(a0), "r"(a1), "r"(a2), "r"(a3), "r"(b0), "r"(b1));
}

__global__ void __launch_bounds__(256, 3) gemm_tc_kernel(const float* __restrict__ attn_l,
                                                         const float* __restrict__ attn_r) {
    extern __shared__ char smem[];
    uint32_t sbase = (uint32_t)__cvta_generic_to_shared(smem);
    int tid = threadIdx.x;
    int lane = tid & 31, wid = tid >> 5;
    int row0 = blockIdx.x * 64;
    int head = blockIdx.y;
    int ncol0 = head * 64;

    if (tid < 64) {
        *(float*)(smem + SM_ATTN_L + tid * 4) = attn_l[ncol0 + tid];
        *(float*)(smem + SM_ATTN_R + tid * 4) = attn_r[ncol0 + tid];
    }
    // ---- stage A (64 rows) via cp.async, OOB rows zero-filled ----
    for (int job = tid; job < 64 * 16; job += 256) {
        int r = job >> 4, c = job & 15;
        int grow = row0 + r;
        uint32_t vsz = (grow < NN) ? 16u : 0u;
        cp_async16(sbase + SM_A_HI + r * ASTR + c * 16,
                   g_hHi + (size_t)grow * 128 + c * 8, vsz);
        cp_async16(sbase + SM_A_LO + r * ASTR + c * 16,
                   g_hLo + (size_t)grow * 128 + c * 8, vsz);
    }
    // ---- stage B (this head's 64 n-rows) via cp.async ----
    for (int job = tid; job < 64 * 16; job += 256) {
        int n = job >> 4, c = job & 15;
        cp_async16(sbase + SM_B_HI + n * ASTR + c * 16,
                   g_WtHi + (ncol0 + n) * 128 + c * 8, 16u);
        cp_async16(sbase + SM_B_LO + n * ASTR + c * 16,
                   g_WtLo + (ncol0 + n) * 128 + c * 8, 16u);
    }
    asm volatile("cp.async.commit_group;" ::: "memory");
    asm volatile("cp.async.wait_group 0;" ::: "memory");
    __syncthreads();

    int g = lane >> 2, tg = lane & 3;
    int wrow = wid & 3;          // row-tile (16 rows each)
    int wcol = wid >> 2;         // col-half (32 cols)
    const char* Arow_hi = smem + SM_A_HI + (uint32_t)(wrow * 16 + g) * ASTR;
    const char* Arow_lo = smem + SM_A_LO + (uint32_t)(wrow * 16 + g) * ASTR;
    float d[4][4];
#pragma unroll
    for (int nt = 0; nt < 4; nt++) { d[nt][0] = d[nt][1] = d[nt][2] = d[nt][3] = 0.f; }

#pragma unroll
    for (int ks = 0; ks < 8; ks++) {
        uint32_t kb = ks * 32 + tg * 4;
        uint32_t ah0 = *(const uint32_t*)(Arow_hi + kb);
        uint32_t ah1 = *(const uint32_t*)(Arow_hi + 8 * ASTR + kb);
        uint32_t ah2 = *(const uint32_t*)(Arow_hi + kb + 16);
        uint32_t ah3 = *(const uint32_t*)(Arow_hi + 8 * ASTR + kb + 16);
        uint32_t al0 = *(const uint32_t*)(Arow_lo + kb);
        uint32_t al1 = *(const uint32_t*)(Arow_lo + 8 * ASTR + kb);
        uint32_t al2 = *(const uint32_t*)(Arow_lo + kb + 16);
        uint32_t al3 = *(const uint32_t*)(Arow_lo + 8 * ASTR + kb + 16);
#pragma unroll
        for (int nt = 0; nt < 4; nt++) {
            uint32_t nb = (uint32_t)((wcol * 4 + nt) * 8 + g) * ASTR + kb;
            uint32_t bh0 = *(const uint32_t*)(smem + SM_B_HI + nb);
            uint32_t bh1 = *(const uint32_t*)(smem + SM_B_HI + nb + 16);
            uint32_t bl0 = *(const uint32_t*)(smem + SM_B_LO + nb);
            uint32_t bl1 = *(const uint32_t*)(smem + SM_B_LO + nb + 16);
            mma_bf16(d[nt], ah0, ah1, ah2, ah3, bh0, bh1);
            mma_bf16(d[nt], al0, al1, al2, al3, bh0, bh1);
            mma_bf16(d[nt], ah0, ah1, ah2, ah3, bl0, bl1);
        }
    }

    // ---- el/er partials over this warp's 32 cols ----
    int r0l = wrow * 16 + g, r1l = r0l + 8;
    float el0 = 0.f, er0 = 0.f, el1 = 0.f, er1 = 0.f;
    const float* alp = (const float*)(smem + SM_ATTN_L);
    const float* arp = (const float*)(smem + SM_ATTN_R);
#pragma unroll
    for (int nt = 0; nt < 4; nt++) {
        int c = (wcol * 4 + nt) * 8 + tg * 2;
        float a0 = alp[c], a1 = alp[c + 1], b0 = arp[c], b1 = arp[c + 1];
        el0 += d[nt][0] * a0 + d[nt][1] * a1;
        er0 += d[nt][0] * b0 + d[nt][1] * b1;
        el1 += d[nt][2] * a0 + d[nt][3] * a1;
        er1 += d[nt][2] * b0 + d[nt][3] * b1;
    }
#pragma unroll
    for (int off = 1; off <= 2; off <<= 1) {
        el0 += __shfl_xor_sync(0xffffffffu, el0, off);
        er0 += __shfl_xor_sync(0xffffffffu, er0, off);
        el1 += __shfl_xor_sync(0xffffffffu, el1, off);
        er1 += __shfl_xor_sync(0xffffffffu, er1, off);
    }
    if (tg == 0) {
        ((float*)(smem + SM_ELB))[r0l * 2 + wcol] = el0;
        ((float*)(smem + SM_ELB))[r1l * 2 + wcol] = el1;
        ((float*)(smem + SM_ERB))[r0l * 2 + wcol] = er0;
        ((float*)(smem + SM_ERB))[r1l * 2 + wcol] = er1;
    }

    // ---- feat: stage fp16 tile in A region ----
    __syncthreads();
    {
#pragma unroll
        for (int nt = 0; nt < 4; nt++) {
            int c = (wcol * 4 + nt) * 8 + tg * 2;
            __half2 q0 = __floats2half2_rn(d[nt][0], d[nt][1]);
            __half2 q1 = __floats2half2_rn(d[nt][2], d[nt][3]);
            *(__half2*)(smem + SM_A_HI + r0l * ASTR + c * 2) = q0;
            *(__half2*)(smem + SM_A_HI + r1l * ASTR + c * 2) = q1;
        }
    }
    __syncthreads();
    // combine el/er partials (threads 0-63, one row each)
    if (tid < 64) {
        int grow = row0 + tid;
        if (grow < NN) {
            float el = ((const float*)(smem + SM_ELB))[tid * 2] +
                       ((const float*)(smem + SM_ELB))[tid * 2 + 1];
            float er = ((const float*)(smem + SM_ERB))[tid * 2] +
                       ((const float*)(smem + SM_ERB))[tid * 2 + 1];
            g_el[2 * grow + head] = el;
            g_er[2 * grow + head] = er;
        }
    }
    // coalesced feat store: 64 rows x 8 chunks of 16B
    for (int job = tid; job < 64 * 8; job += 256) {
        int row = job >> 3, c = job & 7;
        int grow = row0 + row;
        if (grow < NN) {
            *(uint4*)(g_feat16 + (size_t)grow * 128 + ncol0 + c * 8) =
                *(const uint4*)(smem + SM_A_HI + row * ASTR + c * 16);
        }
    }
}

// ---------------- 2: degree histogram ----------------
__global__ void hist_kernel(const int* __restrict__ dst) {
    int e = blockIdx.x * blockDim.x + threadIdx.x;
    if (e < EE) atomicAdd(&g_deg[dst[e]], 1);
}

// ---------------- 3a: per-chunk sums (chunk = 1024) ----------------
__global__ void chunk_sum_kernel() {
    int b = blockIdx.x, t = threadIdx.x;
    int base = b * 1024;
    int s = 0;
    for (int j = t; j < 1024; j += 256) {
        int i = base + j;
        s += (i < NN) ? g_deg[i] : 0;
    }
    __shared__ int sh[8];
#pragma unroll
    for (int off = 16; off; off >>= 1) s += __shfl_xor_sync(0xffffffffu, s, off);
    if ((t & 31) == 0) sh[t >> 5] = s;
    __syncthreads();
    if (t < 32) {
        int v = (t < 8) ? sh[t] : 0;
#pragma unroll
        for (int off = 4; off; off >>= 1) v += __shfl_xor_sync(0xffffffffu, v, off);
        if (t == 0) g_chunk_sum[b] = v;
    }
}

// ---------------- 3b: scan chunk sums (1 block) ----------------
__global__ void scan_chunks_kernel() {
    __shared__ int sh[128];
    int t = threadIdx.x;
    int v = (t < NCHUNK) ? g_chunk_sum[t] : 0;
    sh[t] = v;
    __syncthreads();
    for (int off = 1; off < 128; off <<= 1) {
        int a = (t >= off) ? sh[t - off] : 0;
        __syncthreads();
        sh[t] += a;
        __syncthreads();
    }
    if (t < NCHUNK) g_chunk_excl[t] = sh[t] - v;
}

// ---------------- 3c: finalize row_ptr / cursor ----------------
__global__ void scan_final_kernel() {
    int i = blockIdx.x * 1024 + threadIdx.x;
    int lane = threadIdx.x & 31, wid = threadIdx.x >> 5;
    int v = (i < NN) ? g_deg[i] : 0;
    int x = v;
#pragma unroll
    for (int off = 1; off < 32; off <<= 1) {
        int y = __shfl_up_sync(0xffffffffu, x, off);
        if (lane >= off) x += y;
    }
    __shared__ int sh[32];
    if (lane == 31) sh[wid] = x;
    __syncthreads();
    if (wid == 0) {
        int y = sh[lane];
#pragma unroll
        for (int off = 1; off < 32; off <<= 1) {
            int z = __shfl_up_sync(0xffffffffu, y, off);
            if (lane >= off) y += z;
        }
        sh[lane] = y;
    }
    __syncthreads();
    int incl = x + (wid ? sh[wid - 1] : 0);
    int base = g_chunk_excl[blockIdx.x];
    if (i < NN) {
        int excl = base + incl - v;
        g_rowptr[i] = excl;
        g_cursor[i] = excl;
    }
    if (i == NN - 1) g_rowptr[NN] = base + incl;
}

// ---------------- 4: scatter src indices into CSR order (logit-free) ----------------
__global__ void scatter_idx_kernel(const int* __restrict__ src, const int* __restrict__ dst) {
    int e = blockIdx.x * blockDim.x + threadIdx.x;
    if (e >= EE) return;
    int d = dst[e];
    int p = atomicAdd(&g_cursor[d], 1);
    g_srcIdx[p] = src[e];
}

// ---------------- 5: per-node softmax-aggregate + fused LayerNorm (unroll 4) ----------------
__global__ void agg_ln_kernel(const float* __restrict__ bias, const float* __restrict__ gamma,
                              const float* __restrict__ beta, float* __restrict__ out) {
    int gwarp = (blockIdx.x * blockDim.x + threadIdx.x) >> 5;
    int lane = threadIdx.x & 31;
    if (gwarp >= NN) return;
    int beg = g_rowptr[gwarp], end = g_rowptr[gwarp + 1];
    int hh = (lane >= 16) ? 1 : 0;
    float er_d = g_er[2 * gwarp + hh];

    float4 acc = make_float4(0.f, 0.f, 0.f, 0.f);
    float wsum = 0.f;
    int i = beg;
    for (; i + 4 <= end; i += 4) {
        int s0 = g_srcIdx[i], s1 = g_srcIdx[i + 1], s2 = g_srcIdx[i + 2], s3 = g_srcIdx[i + 3];
        uint2 u0 = ((const uint2*)(g_feat16 + (size_t)s0 * 128))[lane];
        uint2 u1 = ((const uint2*)(g_feat16 + (size_t)s1 * 128))[lane];
        uint2 u2 = ((const uint2*)(g_feat16 + (size_t)s2 * 128))[lane];
        uint2 u3 = ((const uint2*)(g_feat16 + (size_t)s3 * 128))[lane];
        float e0 = g_el[2 * s0 + hh] + er_d;
        float e1 = g_el[2 * s1 + hh] + er_d;
        float e2 = g_el[2 * s2 + hh] + er_d;
        float e3 = g_el[2 * s3 + hh] + er_d;
        e0 = (e0 > 0.f) ? e0 : NEG_SLOPE * e0;
        e1 = (e1 > 0.f) ? e1 : NEG_SLOPE * e1;
        e2 = (e2 > 0.f) ? e2 : NEG_SLOPE * e2;
        e3 = (e3 > 0.f) ? e3 : NEG_SLOPE * e3;
        float w0 = __expf(e0), w1 = __expf(e1), w2 = __expf(e2), w3 = __expf(e3);
        float2 v0a = __half22float2(*(__half2*)&u0.x), v0b = __half22float2(*(__half2*)&u0.y);
        float2 v1a = __half22float2(*(__half2*)&u1.x), v1b = __half22float2(*(__half2*)&u1.y);
        float2 v2a = __half22float2(*(__half2*)&u2.x), v2b = __half22float2(*(__half2*)&u2.y);
        float2 v3a = __half22float2(*(__half2*)&u3.x), v3b = __half22float2(*(__half2*)&u3.y);
        wsum += (w0 + w1) + (w2 + w3);
        acc.x += w0 * v0a.x + w1 * v1a.x + w2 * v2a.x + w3 * v3a.x;
        acc.y += w0 * v0a.y + w1 * v1a.y + w2 * v2a.y + w3 * v3a.y;
        acc.z += w0 * v0b.x + w1 * v1b.x + w2 * v2b.x + w3 * v3b.x;
        acc.w += w0 * v0b.y + w1 * v1b.y + w2 * v2b.y + w3 * v3b.y;
    }
    for (; i < end; i++) {
        int s0 = g_srcIdx[i];
        uint2 u0 = ((const uint2*)(g_feat16 + (size_t)s0 * 128))[lane];
        float e0 = g_el[2 * s0 + hh] + er_d;
        e0 = (e0 > 0.f) ? e0 : NEG_SLOPE * e0;
        float w0 = __expf(e0);
        float2 v0a = __half22float2(*(__half2*)&u0.x);
        float2 v0b = __half22float2(*(__half2*)&u0.y);
        wsum += w0;
        acc.x += w0 * v0a.x; acc.y += w0 * v0a.y;
        acc.z += w0 * v0b.x; acc.w += w0 * v0b.y;
    }
    float inv = (end > beg) ? 1.0f / wsum : 0.f;

    float4 b4 = ((const float4*)bias)[lane];
    float4 x;
    x.x = acc.x * inv + b4.x; x.y = acc.y * inv + b4.y;
    x.z = acc.z * inv + b4.z; x.w = acc.w * inv + b4.w;

    float s = x.x + x.y + x.z + x.w;
#pragma unroll
    for (int off = 16; off; off >>= 1) s += __shfl_xor_sync(0xffffffffu, s, off);
    float mu = s * (1.f / 128.f);
    float dx0 = x.x - mu, dx1 = x.y - mu, dx2 = x.z - mu, dx3 = x.w - mu;
    float ss = dx0 * dx0 + dx1 * dx1 + dx2 * dx2 + dx3 * dx3;
#pragma unroll
    for (int off = 16; off; off >>= 1) ss += __shfl_xor_sync(0xffffffffu, ss, off);
    float istd = rsqrtf(ss * (1.f / 128.f) + LN_EPS);

    float4 g4 = ((const float4*)gamma)[lane];
    float4 be4 = ((const float4*)beta)[lane];
    float4 y;
    y.x = g4.x * dx0 * istd + be4.x;
    y.y = g4.y * dx1 * istd + be4.y;
    y.z = g4.z * dx2 * istd + be4.z;
    y.w = g4.w * dx3 * istd + be4.w;
    ((float4*)(out + (size_t)gwarp * 128))[lane] = y;
}

// ---------------- launch ----------------
extern "C" void kernel_launch(void* const* d_in, const int* in_sizes, int n_in,
                              void* d_out, int out_size) {
    const float* h      = (const float*)d_in[0];
    const int*   src    = (const int*)d_in[1];
    const int*   dst    = (const int*)d_in[2];
    const float* W      = (const float*)d_in[3];
    const float* attn_l = (const float*)d_in[4];
    const float* attn_r = (const float*)d_in[5];
    const float* bias   = (const float*)d_in[6];
    const float* gamma  = (const float*)d_in[7];
    const float* beta   = (const float*)d_in[8];
    float* out = (float*)d_out;

    static cudaStream_t s1 = nullptr;
    static cudaEvent_t evRoot = nullptr, evSide = nullptr;
    if (!s1) {
        cudaStreamCreateWithFlags(&s1, cudaStreamNonBlocking);
        cudaEventCreateWithFlags(&evRoot, cudaEventDisableTiming);
        cudaEventCreateWithFlags(&evSide, cudaEventDisableTiming);
    }
    cudaFuncSetAttribute(gemm_tc_kernel, cudaFuncAttributeMaxDynamicSharedMemorySize, SM_TOTAL);

    // fork point
    cudaEventRecord(evRoot, 0);
    cudaStreamWaitEvent(s1, evRoot, 0);

    // submit: side kernel 0, then main prep+gemm (gemm = submission index 3 for ncu)
    zero_deg_kernel<<<(NN + 255) / 256, 256, 0, s1>>>();               // idx 0
    conv_h_kernel<<<(NN * 32 + 255) / 256, 256>>>(h);                  // idx 1 (main)
    conv_w_kernel<<<64, 256>>>(W);                                     // idx 2 (main)
    {
        dim3 grid((NN + 63) / 64, 2);
        gemm_tc_kernel<<<grid, 256, SM_TOTAL>>>(attn_l, attn_r);       // idx 3 (main)
    }

    // remaining side chain on s1
    hist_kernel<<<(EE + 255) / 256, 256, 0, s1>>>(dst);
    chunk_sum_kernel<<<NCHUNK, 256, 0, s1>>>();
    scan_chunks_kernel<<<1, 128, 0, s1>>>();
    scan_final_kernel<<<NCHUNK, 1024, 0, s1>>>();
    scatter_idx_kernel<<<(EE + 255) / 256, 256, 0, s1>>>(src, dst);
    cudaEventRecord(evSide, s1);

    // join: agg needs feat+el/er (main) + srcIdx (side)
    cudaStreamWaitEvent(0, evSide, 0);
    agg_ln_kernel<<<(NN * 32 + 255) / 256, 256>>>(bias, gamma, beta, out);
}